// round 9
// baseline (speedup 1.0000x reference)
#include <cuda_runtime.h>
#include <math.h>

#define NATOMS 256
#define RCR 5.2f
#define RCA 3.5f
#define PI_F 3.14159265358979323846f
#define CAP_R 96   // radial neighbors (mean ~19)
#define CAP_A 48   // angular neighbors (mean ~5.7)
#define FULL 0xFFFFFFFFu
#define TPB 256    // 8 warps per atom

__global__ void __launch_bounds__(TPB) aev_kernel(
    const float* __restrict__ coords,
    const float* __restrict__ charges,
    float* __restrict__ out)
{
    __shared__ float sc[NATOMS * 3];                          // staged coords (raw x,y,z)
    __shared__ float sq[NATOMS];                              // staged charges
    __shared__ float rd[CAP_R], rw[CAP_R];                    // radial: dist, 0.25*fc*q
    __shared__ float adx[CAP_A], ady[CAP_A], adz[CAP_A];      // angular: i->j vector
    __shared__ float ad[CAP_A], afq[CAP_A];                   // dist, fc*q
    __shared__ int   wcR[8], wcA[8];                          // per-warp counts
    __shared__ float rpart[32][17];                           // warp-0 radial partials
    __shared__ float apart[TPB][33];                          // angular partials (padded)
    __shared__ float tmp0[32], tmp1[32];                      // split-row angular sums

    const int i    = blockIdx.x;
    const int tid  = threadIdx.x;
    const int w    = tid >> 5;
    const int lane = tid & 31;
    const unsigned below = (1u << lane) - 1u;

    // ---------- stage inputs into shared (coalesced float4) ----------
    if (tid < 192) {
        ((float4*)sc)[tid] = ((const float4*)coords)[tid];
    } else {
        ((float4*)sq)[tid - 192] = ((const float4*)charges)[tid - 192];
    }
    __syncthreads();

    const float xi = sc[i * 3 + 0];
    const float yi = sc[i * 3 + 1];
    const float zi = sc[i * 3 + 2];

    // ---------- pass 1: one atom per thread, distances + ballots ----------
    const int j = tid;
    const float dx = sc[j * 3 + 0] - xi;
    const float dy = sc[j * 3 + 1] - yi;
    const float dz = sc[j * 3 + 2] - zi;
    const float d  = sqrtf(dx * dx + dy * dy + dz * dz);
    const float q  = sq[j];
    const bool ok  = (j != i);
    const bool inR = ok && (d < RCR);
    const bool inA = ok && (d < RCA);
    const unsigned mR = __ballot_sync(FULL, inR);
    const unsigned mA = __ballot_sync(FULL, inA);
    if (lane == 0) { wcR[w] = __popc(mR); wcA[w] = __popc(mA); }
    __syncthreads();

    // ---------- pass 2: deterministic compaction + build-time cutoff math ----------
    {
        int baseR = 0, baseA = 0;
        #pragma unroll
        for (int k = 0; k < 8; k++)
            if (k < w) { baseR += wcR[k]; baseA += wcA[k]; }
        if (inR) {
            const int s = baseR + __popc(mR & below);
            const float fc = 0.5f * __cosf((PI_F / RCR) * d) + 0.5f;
            rd[s] = d; rw[s] = 0.25f * fc * q;
        }
        if (inA) {
            const int s = baseA + __popc(mA & below);
            const float fc = 0.5f * __cosf((PI_F / RCA) * d) + 0.5f;
            adx[s] = dx; ady[s] = dy; adz[s] = dz;
            ad[s] = d; afq[s] = fc * q;
        }
    }
    __syncthreads();

    int NR = 0, NA = 0;
    #pragma unroll
    for (int k = 0; k < 8; k++) { NR += wcR[k]; NA += wcA[k]; }

    // ---------- radial: warp 0 consumes list (typ. 1 iteration) ----------
    if (w == 0) {
        float accR[16];
        #pragma unroll
        for (int m = 0; m < 16; m++) accR[m] = 0.0f;
        for (int t = lane; t < NR; t += 32) {
            const float dd = rd[t];
            const float wq = rw[t];
            #pragma unroll
            for (int m = 0; m < 16; m++) {
                const float sh = 0.9f + 0.26875f * (float)m;
                const float u  = dd - sh;
                accR[m] += wq * __expf(-16.0f * u * u);
            }
        }
        #pragma unroll
        for (int m = 0; m < 16; m++) rpart[lane][m] = accR[m];
    }

    // ---------- angular: pair-per-lane, reversed mapping (lands on high warps) ----------
    float accA[32];
    #pragma unroll
    for (int s = 0; s < 32; s++) accA[s] = 0.0f;

    const int M  = NA;
    const int PP = M * M;
    const float fM = (float)M;
    for (int p = (TPB - 1) - tid; p < PP; p += TPB) {
        // float division exact enough for p < 2^12, M >= 2 (err 1/M >> ulp)
        const int a = (int)(__fdividef((float)p, fM));
        const int b = p - a * M;
        if (a >= b) continue;  // unordered pairs; reference double-counts ordered -> x2

        const float da = ad[a], db = ad[b];
        const float dot = adx[a] * adx[b] + ady[a] * ady[b] + adz[a] * adz[b];
        const float cth = 0.95f * __fdividef(dot, da * db);      // |cth| <= 0.95
        const float sth = sqrtf(fmaxf(1.0f - cth * cth, 0.0f));  // theta in [0,pi]
        const float wgt = 2.0f * afq[a] * afq[b];
        const float davg = 0.5f * (da + db);

        #pragma unroll
        for (int az = 0; az < 4; az++) {
            const float sha = 0.9f + 0.65f * (float)az;
            const float u   = davg - sha;
            const float rad = wgt * __expf(-8.0f * u * u);
            #pragma unroll
            for (int zz = 0; zz < 8; zz++) {
                const float ang = PI_F / 16.0f + (PI_F / 8.0f) * (float)zz;
                const float cz  = cosf(ang);   // compile-time constants
                const float sz  = sinf(ang);
                // cos(theta - ShfZ) = cth*cos(ShfZ) + sin(theta)*sin(ShfZ)  (exact)
                const float x   = 0.5f * (1.0f + cth * cz + sth * sz);
                const float x2  = x * x;
                const float x4  = x2 * x2;
                const float x8  = x4 * x4;
                const float x16 = x8 * x8;
                accA[az * 8 + zz] += rad * (x16 * x16);
            }
        }
    }

    #pragma unroll
    for (int s = 0; s < 32; s++) apart[tid][s] = accA[s];
    __syncthreads();

    // ---------- split-row reductions ----------
    if (tid < 32) {
        // angular columns, rows 0..127
        float v0 = 0.f, v1 = 0.f, v2 = 0.f, v3 = 0.f;
        float v4 = 0.f, v5 = 0.f, v6 = 0.f, v7 = 0.f;
        #pragma unroll
        for (int l = 0; l < 128; l += 8) {
            v0 += apart[l + 0][tid]; v1 += apart[l + 1][tid];
            v2 += apart[l + 2][tid]; v3 += apart[l + 3][tid];
            v4 += apart[l + 4][tid]; v5 += apart[l + 5][tid];
            v6 += apart[l + 6][tid]; v7 += apart[l + 7][tid];
        }
        tmp0[tid] = ((v0 + v1) + (v2 + v3)) + ((v4 + v5) + (v6 + v7));
    } else if (tid < 64) {
        // angular columns, rows 128..255
        const int c = tid - 32;
        float v0 = 0.f, v1 = 0.f, v2 = 0.f, v3 = 0.f;
        float v4 = 0.f, v5 = 0.f, v6 = 0.f, v7 = 0.f;
        #pragma unroll
        for (int l = 128; l < 256; l += 8) {
            v0 += apart[l + 0][c]; v1 += apart[l + 1][c];
            v2 += apart[l + 2][c]; v3 += apart[l + 3][c];
            v4 += apart[l + 4][c]; v5 += apart[l + 5][c];
            v6 += apart[l + 6][c]; v7 += apart[l + 7][c];
        }
        tmp1[c] = ((v0 + v1) + (v2 + v3)) + ((v4 + v5) + (v6 + v7));
    } else if (tid < 80) {
        // radial: sum warp-0's 32 rows, write directly
        const int m = tid - 64;
        float v0 = 0.f, v1 = 0.f, v2 = 0.f, v3 = 0.f;
        #pragma unroll
        for (int l = 0; l < 32; l += 4) {
            v0 += rpart[l + 0][m]; v1 += rpart[l + 1][m];
            v2 += rpart[l + 2][m]; v3 += rpart[l + 3][m];
        }
        out[i * 48 + m] = (v0 + v1) + (v2 + v3);
    }
    __syncthreads();

    if (tid < 32) out[i * 48 + 16 + tid] = tmp0[tid] + tmp1[tid];
}

extern "C" void kernel_launch(void* const* d_in, const int* in_sizes, int n_in,
                              void* d_out, int out_size) {
    const float* coords  = (const float*)d_in[0];  // [256,3] fp32
    const float* charges = (const float*)d_in[1];  // [256]   fp32
    float* out = (float*)d_out;                    // [256,48] fp32
    aev_kernel<<<NATOMS, TPB>>>(coords, charges, out);
}

// round 10
// speedup vs baseline: 1.1535x; 1.1535x over previous
#include <cuda_runtime.h>
#include <math.h>

#define NATOMS 256
#define RCR 5.2f
#define RCA 3.5f
#define PI_F 3.14159265358979323846f
#define FULL 0xFFFFFFFFu
#define TPB 128    // 4 warps per atom
#define NREP (NATOMS / TPB)   // 2

__global__ void __launch_bounds__(TPB) aev_kernel(
    const float* __restrict__ coords,
    const float* __restrict__ charges,
    float* __restrict__ out)
{
    __shared__ float rd[96], rw[96];                          // radial: dist, 0.25*fc*q
    __shared__ float adx[48], ady[48], adz[48];               // angular: i->j vector
    __shared__ float ad[48], afq[48];                         // dist, fc*q
    __shared__ int   wcR[NREP * 4], wcA[NREP * 4];            // per (rep,warp) counts
    __shared__ float part[TPB][49];                           // padded transpose buffer

    const int i    = blockIdx.x;
    const int tid  = threadIdx.x;
    const int w    = tid >> 5;
    const int lane = tid & 31;
    const unsigned below = (1u << lane) - 1u;

    const float xi = __ldg(&coords[i * 3 + 0]);
    const float yi = __ldg(&coords[i * 3 + 1]);
    const float zi = __ldg(&coords[i * 3 + 2]);

    // ---------- pass 1: distances + ballots (deterministic ordering) ----------
    float dxv[NREP], dyv[NREP], dzv[NREP], dv[NREP], qv[NREP];
    unsigned mRv[NREP], mAv[NREP];
    bool inRv[NREP], inAv[NREP];

    #pragma unroll
    for (int rep = 0; rep < NREP; rep++) {
        const int j = rep * TPB + tid;
        const float dx = __ldg(&coords[j * 3 + 0]) - xi;
        const float dy = __ldg(&coords[j * 3 + 1]) - yi;
        const float dz = __ldg(&coords[j * 3 + 2]) - zi;
        const float d  = sqrtf(dx * dx + dy * dy + dz * dz);
        const bool ok  = (j != i);
        const bool inR = ok && (d < RCR);
        const bool inA = ok && (d < RCA);
        dxv[rep] = dx; dyv[rep] = dy; dzv[rep] = dz; dv[rep] = d;
        qv[rep]  = __ldg(&charges[j]);
        inRv[rep] = inR; inAv[rep] = inA;
        mRv[rep] = __ballot_sync(FULL, inR);
        mAv[rep] = __ballot_sync(FULL, inA);
        if (lane == 0) {
            wcR[rep * 4 + w] = __popc(mRv[rep]);
            wcA[rep * 4 + w] = __popc(mAv[rep]);
        }
    }
    __syncthreads();

    // ---------- pass 2: exclusive-prefix bases + compacted writes (+fc math) ----------
    #pragma unroll
    for (int rep = 0; rep < NREP; rep++) {
        const int seg = rep * 4 + w;
        int baseR = 0, baseA = 0;
        #pragma unroll
        for (int k = 0; k < NREP * 4; k++)
            if (k < seg) { baseR += wcR[k]; baseA += wcA[k]; }
        if (inRv[rep]) {
            const int s = baseR + __popc(mRv[rep] & below);
            const float d  = dv[rep];
            const float fc = 0.5f * __cosf((PI_F / RCR) * d) + 0.5f;
            rd[s] = d; rw[s] = 0.25f * fc * qv[rep];
        }
        if (inAv[rep]) {
            const int s = baseA + __popc(mAv[rep] & below);
            const float d  = dv[rep];
            const float fc = 0.5f * __cosf((PI_F / RCA) * d) + 0.5f;
            adx[s] = dxv[rep]; ady[s] = dyv[rep]; adz[s] = dzv[rep];
            ad[s] = d; afq[s] = fc * qv[rep];
        }
    }
    __syncthreads();

    int NR = 0, NA = 0;
    #pragma unroll
    for (int k = 0; k < NREP * 4; k++) { NR += wcR[k]; NA += wcA[k]; }

    // ---------- radial: neighbor-per-lane, 16 slots serial (high ILP) ----------
    float accR[16];
    #pragma unroll
    for (int m = 0; m < 16; m++) accR[m] = 0.0f;

    for (int t = tid; t < NR; t += TPB) {
        const float d  = rd[t];
        const float wq = rw[t];
        #pragma unroll
        for (int m = 0; m < 16; m++) {
            const float sh = 0.9f + 0.26875f * (float)m;
            const float u  = d - sh;
            accR[m] += wq * __expf(-16.0f * u * u);
        }
    }

    // ---------- angular: triangular pair-per-lane (no wasted lanes) ----------
    float accA[32];
    #pragma unroll
    for (int s = 0; s < 32; s++) accA[s] = 0.0f;

    const int M   = NA;
    const int PPh = (M * (M - 1)) >> 1;   // unordered pairs; ref double-counts -> x2 in wgt
    for (int k = tid; k < PPh; k += TPB) {
        // decode triangular index: k = b(b-1)/2 + a, 0 <= a < b
        int b = (int)(0.5f * (1.0f + sqrtf(8.0f * (float)k + 1.0f)));
        int tb = (b * (b - 1)) >> 1;
        if (k < tb)           { b--; tb = (b * (b - 1)) >> 1; }
        else if (k >= tb + b) { b++; tb = (b * (b - 1)) >> 1; }
        const int a = k - tb;

        const float da = ad[a], db = ad[b];
        const float dot = adx[a] * adx[b] + ady[a] * ady[b] + adz[a] * adz[b];
        const float cth = 0.95f * __fdividef(dot, da * db);      // |cth| <= 0.95
        const float sth = sqrtf(fmaxf(1.0f - cth * cth, 0.0f));  // theta in [0,pi]
        const float wgt = 2.0f * afq[a] * afq[b];
        const float davg = 0.5f * (da + db);

        #pragma unroll
        for (int az = 0; az < 4; az++) {
            const float sha = 0.9f + 0.65f * (float)az;
            const float u   = davg - sha;
            const float rad = wgt * __expf(-8.0f * u * u);
            #pragma unroll
            for (int zz = 0; zz < 8; zz++) {
                const float ang = PI_F / 16.0f + (PI_F / 8.0f) * (float)zz;
                const float cz  = cosf(ang);   // compile-time constants
                const float sz  = sinf(ang);
                // cos(theta - ShfZ) = cth*cos(ShfZ) + sin(theta)*sin(ShfZ)  (exact)
                const float x   = 0.5f * (1.0f + cth * cz + sth * sz);
                const float x2  = x * x;
                const float x4  = x2 * x2;
                const float x8  = x4 * x4;
                const float x16 = x8 * x8;
                accA[az * 8 + zz] += rad * (x16 * x16);
            }
        }
    }

    // ---------- shared transpose ----------
    #pragma unroll
    for (int m = 0; m < 16; m++) part[tid][m] = accR[m];
    #pragma unroll
    for (int s = 0; s < 32; s++) part[tid][16 + s] = accA[s];
    __syncthreads();

    // ---------- bounded 8-way-ILP column sums ----------
    // only rows tid < NR (radial) / tid < PPh (angular) are nonzero; rows
    // beyond hold stored zeros, so rounding the bound up to 8 is safe.
    if (tid < 48) {
        const int rawB = (tid < 16) ? NR : PPh;
        const int bnd  = (min(rawB, TPB) + 7) & ~7;
        float v0 = 0.f, v1 = 0.f, v2 = 0.f, v3 = 0.f;
        float v4 = 0.f, v5 = 0.f, v6 = 0.f, v7 = 0.f;
        for (int l = 0; l < bnd; l += 8) {
            v0 += part[l + 0][tid];
            v1 += part[l + 1][tid];
            v2 += part[l + 2][tid];
            v3 += part[l + 3][tid];
            v4 += part[l + 4][tid];
            v5 += part[l + 5][tid];
            v6 += part[l + 6][tid];
            v7 += part[l + 7][tid];
        }
        out[i * 48 + tid] = ((v0 + v1) + (v2 + v3)) + ((v4 + v5) + (v6 + v7));
    }
}

extern "C" void kernel_launch(void* const* d_in, const int* in_sizes, int n_in,
                              void* d_out, int out_size) {
    const float* coords  = (const float*)d_in[0];  // [256,3] fp32
    const float* charges = (const float*)d_in[1];  // [256]   fp32
    float* out = (float*)d_out;                    // [256,48] fp32
    aev_kernel<<<NATOMS, TPB>>>(coords, charges, out);
}

// round 11
// speedup vs baseline: 1.2098x; 1.0488x over previous
#include <cuda_runtime.h>
#include <math.h>

#define NATOMS 256
#define RCR 5.2f
#define RCA 3.5f
#define PI_F 3.14159265358979323846f
#define FULL 0xFFFFFFFFu
#define TPB 128    // 4 warps per atom
#define NREP (NATOMS / TPB)   // 2

typedef unsigned long long u64;
#define PACK2(o, lo, hi) asm("mov.b64 %0, {%1, %2};" : "=l"(o) : "f"(lo), "f"(hi))
#define UNPACK2(lo, hi, in) asm("mov.b64 {%0, %1}, %2;" : "=f"(lo), "=f"(hi) : "l"(in))
#define MUL2(o, a, b) asm("mul.rn.f32x2 %0, %1, %2;" : "=l"(o) : "l"(a), "l"(b))
#define FMA2(o, a, b, c) asm("fma.rn.f32x2 %0, %1, %2, %3;" : "=l"(o) : "l"(a), "l"(b), "l"(c))

__global__ void __launch_bounds__(TPB) aev_kernel(
    const float* __restrict__ coords,
    const float* __restrict__ charges,
    float* __restrict__ out)
{
    __shared__ float rd[96], rw[96];                          // radial: dist, 0.25*fc*q
    __shared__ float adx[48], ady[48], adz[48];               // angular: i->j vector
    __shared__ float ad[48], afq[48];                         // dist, fc*q
    __shared__ int   wcR[NREP * 4], wcA[NREP * 4];            // per (rep,warp) counts
    __shared__ float part[TPB][49];                           // padded transpose buffer

    const int i    = blockIdx.x;
    const int tid  = threadIdx.x;
    const int w    = tid >> 5;
    const int lane = tid & 31;
    const unsigned below = (1u << lane) - 1u;

    const float xi = __ldg(&coords[i * 3 + 0]);
    const float yi = __ldg(&coords[i * 3 + 1]);
    const float zi = __ldg(&coords[i * 3 + 2]);

    // ---------- pass 1: distances + ballots (deterministic ordering) ----------
    float dxv[NREP], dyv[NREP], dzv[NREP], dv[NREP], qv[NREP];
    unsigned mRv[NREP], mAv[NREP];
    bool inRv[NREP], inAv[NREP];

    #pragma unroll
    for (int rep = 0; rep < NREP; rep++) {
        const int j = rep * TPB + tid;
        const float dx = __ldg(&coords[j * 3 + 0]) - xi;
        const float dy = __ldg(&coords[j * 3 + 1]) - yi;
        const float dz = __ldg(&coords[j * 3 + 2]) - zi;
        const float d  = sqrtf(dx * dx + dy * dy + dz * dz);
        const bool ok  = (j != i);
        const bool inR = ok && (d < RCR);
        const bool inA = ok && (d < RCA);
        dxv[rep] = dx; dyv[rep] = dy; dzv[rep] = dz; dv[rep] = d;
        qv[rep]  = __ldg(&charges[j]);
        inRv[rep] = inR; inAv[rep] = inA;
        mRv[rep] = __ballot_sync(FULL, inR);
        mAv[rep] = __ballot_sync(FULL, inA);
        if (lane == 0) {
            wcR[rep * 4 + w] = __popc(mRv[rep]);
            wcA[rep * 4 + w] = __popc(mAv[rep]);
        }
    }
    __syncthreads();

    // ---------- pass 2: exclusive-prefix bases + compacted writes (+fc math) ----------
    #pragma unroll
    for (int rep = 0; rep < NREP; rep++) {
        const int seg = rep * 4 + w;
        int baseR = 0, baseA = 0;
        #pragma unroll
        for (int k = 0; k < NREP * 4; k++)
            if (k < seg) { baseR += wcR[k]; baseA += wcA[k]; }
        if (inRv[rep]) {
            const int s = baseR + __popc(mRv[rep] & below);
            const float d  = dv[rep];
            const float fc = 0.5f * __cosf((PI_F / RCR) * d) + 0.5f;
            rd[s] = d; rw[s] = 0.25f * fc * qv[rep];
        }
        if (inAv[rep]) {
            const int s = baseA + __popc(mAv[rep] & below);
            const float d  = dv[rep];
            const float fc = 0.5f * __cosf((PI_F / RCA) * d) + 0.5f;
            adx[s] = dxv[rep]; ady[s] = dyv[rep]; adz[s] = dzv[rep];
            ad[s] = d; afq[s] = fc * qv[rep];
        }
    }
    __syncthreads();

    int NR = 0, NA = 0;
    #pragma unroll
    for (int k = 0; k < NREP * 4; k++) { NR += wcR[k]; NA += wcA[k]; }

    // ---------- radial: neighbor-per-lane, 16 slots serial (high ILP) ----------
    float accR[16];
    #pragma unroll
    for (int m = 0; m < 16; m++) accR[m] = 0.0f;

    for (int t = tid; t < NR; t += TPB) {
        const float d  = rd[t];
        const float wq = rw[t];
        #pragma unroll
        for (int m = 0; m < 16; m++) {
            const float sh = 0.9f + 0.26875f * (float)m;
            const float u  = d - sh;
            accR[m] += wq * __expf(-16.0f * u * u);
        }
    }

    // ---------- angular: triangular pair-per-lane, packed f32x2 slot math ----------
    // 0.5*cos(ShfZ) / 0.5*sin(ShfZ) for ShfZ = pi/16 + (pi/8)*z, z = 0..7,
    // packed in (z, z+1) pairs.
    u64 CZ2[4], SZ2[4], HALF2;
    PACK2(CZ2[0],  0.49039264f,  0.41573481f);
    PACK2(CZ2[1],  0.27778512f,  0.09754516f);
    PACK2(CZ2[2], -0.09754516f, -0.27778512f);
    PACK2(CZ2[3], -0.41573481f, -0.49039264f);
    PACK2(SZ2[0],  0.09754516f,  0.27778512f);
    PACK2(SZ2[1],  0.41573481f,  0.49039264f);
    PACK2(SZ2[2],  0.49039264f,  0.41573481f);
    PACK2(SZ2[3],  0.27778512f,  0.09754516f);
    PACK2(HALF2, 0.5f, 0.5f);

    u64 accA2[16];
    #pragma unroll
    for (int s = 0; s < 16; s++) accA2[s] = 0ull;

    const int M   = NA;
    const int PPh = (M * (M - 1)) >> 1;   // unordered pairs; ref double-counts -> x2 in wgt
    for (int k = tid; k < PPh; k += TPB) {
        // decode triangular index: k = b(b-1)/2 + a, 0 <= a < b
        int b = (int)(0.5f * (1.0f + sqrtf(8.0f * (float)k + 1.0f)));
        int tb = (b * (b - 1)) >> 1;
        if (k < tb)           { b--; tb = (b * (b - 1)) >> 1; }
        else if (k >= tb + b) { b++; tb = (b * (b - 1)) >> 1; }
        const int a = k - tb;

        const float da = ad[a], db = ad[b];
        const float dot = adx[a] * adx[b] + ady[a] * ady[b] + adz[a] * adz[b];
        const float cth = 0.95f * __fdividef(dot, da * db);      // |cth| <= 0.95
        const float sth = sqrtf(fmaxf(1.0f - cth * cth, 0.0f));  // theta in [0,pi]
        const float wgt = 2.0f * afq[a] * afq[b];
        const float davg = 0.5f * (da + db);

        u64 cth2, sth2;
        PACK2(cth2, cth, cth);
        PACK2(sth2, sth, sth);

        #pragma unroll
        for (int az = 0; az < 4; az++) {
            const float sha = 0.9f + 0.65f * (float)az;
            const float u   = davg - sha;
            const float rad = wgt * __expf(-8.0f * u * u);
            u64 rad2;
            PACK2(rad2, rad, rad);
            #pragma unroll
            for (int p = 0; p < 4; p++) {
                // x = 0.5 + cth*0.5cos(ShfZ) + sth*0.5sin(ShfZ)   (exact identity
                // for 0.5*(1+cos(theta-ShfZ)), theta in [0,pi])
                u64 x, t;
                FMA2(t, sth2, SZ2[p], HALF2);
                FMA2(x, cth2, CZ2[p], t);
                MUL2(x, x, x);   // x^2
                MUL2(x, x, x);   // x^4
                MUL2(x, x, x);   // x^8
                MUL2(x, x, x);   // x^16
                MUL2(x, x, x);   // x^32
                FMA2(accA2[az * 4 + p], rad2, x, accA2[az * 4 + p]);
            }
        }
    }

    // ---------- shared transpose ----------
    #pragma unroll
    for (int m = 0; m < 16; m++) part[tid][m] = accR[m];
    #pragma unroll
    for (int s = 0; s < 16; s++) {
        float lo, hi;
        UNPACK2(lo, hi, accA2[s]);
        part[tid][16 + 2 * s]     = lo;
        part[tid][16 + 2 * s + 1] = hi;
    }
    __syncthreads();

    // ---------- bounded 8-way-ILP column sums ----------
    // only rows tid < NR (radial) / tid < PPh (angular) are nonzero; rows
    // beyond hold stored zeros, so rounding the bound up to 8 is safe.
    if (tid < 48) {
        const int rawB = (tid < 16) ? NR : PPh;
        const int bnd  = (min(rawB, TPB) + 7) & ~7;
        float v0 = 0.f, v1 = 0.f, v2 = 0.f, v3 = 0.f;
        float v4 = 0.f, v5 = 0.f, v6 = 0.f, v7 = 0.f;
        for (int l = 0; l < bnd; l += 8) {
            v0 += part[l + 0][tid];
            v1 += part[l + 1][tid];
            v2 += part[l + 2][tid];
            v3 += part[l + 3][tid];
            v4 += part[l + 4][tid];
            v5 += part[l + 5][tid];
            v6 += part[l + 6][tid];
            v7 += part[l + 7][tid];
        }
        out[i * 48 + tid] = ((v0 + v1) + (v2 + v3)) + ((v4 + v5) + (v6 + v7));
    }
}

extern "C" void kernel_launch(void* const* d_in, const int* in_sizes, int n_in,
                              void* d_out, int out_size) {
    const float* coords  = (const float*)d_in[0];  // [256,3] fp32
    const float* charges = (const float*)d_in[1];  // [256]   fp32
    float* out = (float*)d_out;                    // [256,48] fp32
    aev_kernel<<<NATOMS, TPB>>>(coords, charges, out);
}